// round 11
// baseline (speedup 1.0000x reference)
#include <cuda_runtime.h>
#include <cuda_bf16.h>
#include <math.h>

#define NN 6000
#define EE 100000

// ---------------- scratch (device-only; NEVER passed from host) ----------------
__device__ float g_x[NN * 64];          // ping
__device__ float g_y[NN * 64];          // pong
__device__ float g_hr[2 * NN * 32];     // layer0 relation rows
__device__ float g_W1[32 * 128];        // [I, 2*O]
__device__ float g_W2[64 * 128];
__device__ float g_W3[64 * 64];
__device__ int   g_cnt[2 * NN];
__device__ float g_rinv[2 * NN];
__device__ int   g_offs[NN + 1];
__device__ int   g_cur[NN];
__device__ int   g_csr[EE];             // src | (rel<<16)
__device__ float g_h[NN * 512];
__device__ float g_asv[NN], g_adv[NN];
__device__ float g_o512[NN * 512];      // holds relu(gat_out + gbias)
__device__ float g_A[NN * 128], g_B[NN * 128];

// ---------------- fused init: zero counters + all weight precomputes ----------------
__device__ __forceinline__ void wcat_one(float* W, const float* basis, const float* comp,
                                         int I, int O, int i) {
    int r = i / (I * O), io = i % (I * O);
    float acc = 0.f;
#pragma unroll
    for (int b = 0; b < 4; b++) acc += comp[r * 4 + b] * basis[b * I * O + io];
    W[(io / O) * 2 * O + r * O + (io % O)] = acc;
}
#define R0 (2 * NN * 32)
__global__ void init_k(const float* __restrict__ basis0, const float* __restrict__ comp0,
                       const float* __restrict__ b1s, const float* __restrict__ c1,
                       const float* __restrict__ b2s, const float* __restrict__ c2,
                       const float* __restrict__ b3s, const float* __restrict__ c3) {
    int i = blockIdx.x * blockDim.x + threadIdx.x;
    if (i < 2 * NN) g_cnt[i] = 0;
    if (i < NN) { g_cur[i] = 0; g_asv[i] = 0.f; g_adv[i] = 0.f; }
    if (i < R0) {
        int r = i / (NN * 32), idx = i % (NN * 32);
        float acc = 0.f;
#pragma unroll
        for (int b = 0; b < 4; b++) acc += comp0[r * 4 + b] * basis0[b * NN * 32 + idx];
        g_hr[r * NN * 32 + idx] = acc;
    } else if (i < R0 + 4096) {
        wcat_one(g_W1, b1s, c1, 32, 64, i - R0);
    } else if (i < R0 + 4096 + 8192) {
        wcat_one(g_W2, b2s, c2, 64, 64, i - R0 - 4096);
    } else if (i < R0 + 4096 + 8192 + 4096) {
        wcat_one(g_W3, b3s, c3, 64, 32, i - R0 - 4096 - 8192);
    }
}

__global__ void count_k(const int* __restrict__ et, const int* __restrict__ dst) {
    int e = blockIdx.x * blockDim.x + threadIdx.x;
    if (e < EE) atomicAdd(&g_cnt[et[e] * NN + dst[e]], 1);
}
// scan of deg (=cnt0+cnt1) + rinv, single block 1024 threads
__global__ void scan_k() {
    __shared__ int ws[32];
    int t = threadIdx.x;
    for (int i = t; i < 2 * NN; i += 1024)
        g_rinv[i] = 1.0f / fmaxf((float)g_cnt[i], 1.0f);
    int base = t * 6;
    int loc[6]; int s = 0;
#pragma unroll
    for (int j = 0; j < 6; j++) {
        int idx = base + j; loc[j] = s;
        s += (idx < NN) ? (g_cnt[idx] + g_cnt[NN + idx]) : 0;
    }
    int lane = t & 31, w = t >> 5;
    int v = s;
#pragma unroll
    for (int off = 1; off < 32; off <<= 1) {
        int nv = __shfl_up_sync(0xffffffffu, v, off);
        if (lane >= off) v += nv;
    }
    if (lane == 31) ws[w] = v;
    __syncthreads();
    if (w == 0) {
        int x = ws[lane];
#pragma unroll
        for (int off = 1; off < 32; off <<= 1) {
            int nv = __shfl_up_sync(0xffffffffu, x, off);
            if (lane >= off) x += nv;
        }
        ws[lane] = x;
    }
    __syncthreads();
    int excl = v - s + (w ? ws[w - 1] : 0);
#pragma unroll
    for (int j = 0; j < 6; j++) {
        int idx = base + j;
        if (idx < NN) g_offs[idx] = excl + loc[j];
    }
    if (t == 1023) g_offs[NN] = excl + s;
}
__global__ void scatter_k(const int* __restrict__ src, const int* __restrict__ dst,
                          const int* __restrict__ et) {
    int e = blockIdx.x * blockDim.x + threadIdx.x;
    if (e >= EE) return;
    int d = dst[e];
    int pos = g_offs[d] + atomicAdd(&g_cur[d], 1);
    g_csr[pos] = src[e] | (et[e] << 16);
}

// ---------------- layer 0: gather + root + bias + tanh ----------------
__global__ void l0_agg_k(const float* __restrict__ root0, const float* __restrict__ rbias0) {
    int n = blockIdx.x * 4 + (threadIdx.x >> 5);
    int lane = threadIdx.x & 31;
    if (n >= NN) return;
    int o = g_offs[n], e2 = g_offs[n + 1];
    float a0 = 0.f, a1 = 0.f;
    for (int p = o; p < e2; p++) {
        int pk = g_csr[p];
        float v = g_hr[(pk >> 16) * NN * 32 + (pk & 0xffff) * 32 + lane];
        if (pk & 0x10000) a1 += v; else a0 += v;
    }
    float out = root0[n * 32 + lane] + rbias0[lane] + a0 * g_rinv[n] + a1 * g_rinv[NN + n];
    g_x[n * 32 + lane] = tanhf(out);
}

// ---------------- fused RGCN layer: aggregate + GEMM + tanh ----------------
__global__ void layer_k(const float* __restrict__ root, const float* __restrict__ rbias,
                        int layer, int I, int O, int inflag) {
    __shared__ float xs[4][64], a0s[4][64], a1s[4][64];
    const float* xin = inflag ? g_y : g_x;
    float* xout = inflag ? g_x : g_y;
    const float* Wcat = (layer == 1) ? g_W1 : (layer == 2) ? g_W2 : g_W3;
    int ty = threadIdx.y, tx = threadIdx.x;
    int n = blockIdx.x * 4 + ty;
    if (tx < I) {
        int o = g_offs[n], e2 = g_offs[n + 1];
        float a0 = 0.f, a1 = 0.f;
#pragma unroll 4
        for (int p = o; p < e2; p++) {
            int pk = g_csr[p];
            float v = xin[(pk & 0xffff) * I + tx];
            if (pk & 0x10000) a1 += v; else a0 += v;
        }
        xs[ty][tx] = xin[n * I + tx];
        a0s[ty][tx] = a0 * g_rinv[n];
        a1s[ty][tx] = a1 * g_rinv[NN + n];
    }
    __syncthreads();
    if (tx < O) {
        float acc = rbias[tx];
#pragma unroll 8
        for (int i = 0; i < I; i++) {
            acc += xs[ty][i] * root[i * O + tx];
            acc += a0s[ty][i] * Wcat[i * 2 * O + tx];
            acc += a1s[ty][i] * Wcat[i * 2 * O + O + tx];
        }
        xout[n * O + tx] = tanhf(acc);
    }
}

// ---------------- GAT h GEMM + fused attention partials ----------------
__global__ void gath_gemm_k(const float* __restrict__ gw, const float* __restrict__ asrc,
                            const float* __restrict__ adst) {
    __shared__ float As[32][68];
    __shared__ float Bs[32][128];
    int tid = threadIdx.x;
    int bm = blockIdx.x * 64, bn = blockIdx.y * 128;
    int ty = tid >> 4, tx = tid & 15;
    {
        int mm = tid & 63, kg = tid >> 6;
#pragma unroll
        for (int r = 0; r < 2; r++) {
            int k = kg * 8 + r * 4;
            int gm = bm + mm;
            float4 v = make_float4(0.f, 0.f, 0.f, 0.f);
            if (gm < NN) v = *(const float4*)&g_y[gm * 32 + k];
            As[k + 0][mm] = v.x; As[k + 1][mm] = v.y;
            As[k + 2][mm] = v.z; As[k + 3][mm] = v.w;
        }
    }
    {
        int id = tid * 4;
#pragma unroll
        for (int rep = 0; rep < 4; rep++, id += 1024) {
            int kk = id >> 7, col = id & 127;
            *(float4*)&Bs[kk][col] = *(const float4*)&gw[kk * 512 + bn + col];
        }
    }
    __syncthreads();
    float acc[4][8] = {};
#pragma unroll
    for (int kk = 0; kk < 32; kk++) {
        float a[4], bb[8];
#pragma unroll
        for (int i = 0; i < 4; i++) a[i] = As[kk][ty * 4 + i];
#pragma unroll
        for (int j = 0; j < 8; j++) bb[j] = Bs[kk][tx * 8 + j];
#pragma unroll
        for (int i = 0; i < 4; i++)
#pragma unroll
            for (int j = 0; j < 8; j++) acc[i][j] += a[i] * bb[j];
    }
#pragma unroll
    for (int i = 0; i < 4; i++) {
        int gm = bm + ty * 4 + i;
        if (gm >= NN) continue;
#pragma unroll
        for (int j = 0; j < 8; j += 4) {
            float4 st = make_float4(acc[i][j], acc[i][j + 1], acc[i][j + 2], acc[i][j + 3]);
            *(float4*)&g_h[gm * 512 + bn + tx * 8 + j] = st;
        }
    }
    float sa[8], da[8];
#pragma unroll
    for (int j = 0; j < 8; j++) {
        sa[j] = asrc[bn + tx * 8 + j];
        da[j] = adst[bn + tx * 8 + j];
    }
#pragma unroll
    for (int i = 0; i < 4; i++) {
        float pa = 0.f, pd = 0.f;
#pragma unroll
        for (int j = 0; j < 8; j++) { pa += acc[i][j] * sa[j]; pd += acc[i][j] * da[j]; }
#pragma unroll
        for (int off = 8; off; off >>= 1) {
            pa += __shfl_down_sync(0xffffffffu, pa, off, 16);
            pd += __shfl_down_sync(0xffffffffu, pd, off, 16);
        }
        int gm = bm + ty * 4 + i;
        if (tx == 0 && gm < NN) {
            atomicAdd(&g_asv[gm], pa);
            atomicAdd(&g_adv[gm], pd);
        }
    }
}

// ---------------- GAT softmax + weighted sum + fused gbias/relu ----------------
// 4 nodes / 128-thread block; warp per node; shfl-only reductions.
__global__ void gat_node_k(const float* __restrict__ gbias) {
    __shared__ float sal[4][512];
    __shared__ int ssrc[4][512];
    int wid = threadIdx.x >> 5, lane = threadIdx.x & 31;
    int n = blockIdx.x * 4 + wid;
    if (n >= NN) return;
    int o = g_offs[n];
    int deg = g_offs[n + 1] - o;
    if (deg > 512) deg = 512;
    float advn = g_adv[n];
    float* wsal = sal[wid];
    int* wsrc = ssrc[wid];
    float lm = -1e30f;
    for (int p = lane; p < deg; p += 32) {
        int s = g_csr[o + p] & 0xffff;
        wsrc[p] = s;
        float a = g_asv[s] + advn;
        a = a > 0.f ? a : 0.2f * a;
        wsal[p] = a;
        lm = fmaxf(lm, a);
    }
    float als = g_asv[n] + advn;
    als = als > 0.f ? als : 0.2f * als;
    lm = fmaxf(lm, als);
#pragma unroll
    for (int off = 16; off; off >>= 1)
        lm = fmaxf(lm, __shfl_xor_sync(0xffffffffu, lm, off));
    float m = lm;
    float ls = 0.f;
    __syncwarp();
    for (int p = lane; p < deg; p += 32) {
        float ex = expf(wsal[p] - m);
        wsal[p] = ex;
        ls += ex;
    }
    float exs = expf(als - m);
    if (lane == 0) ls += exs;
#pragma unroll
    for (int off = 16; off; off >>= 1)
        ls += __shfl_xor_sync(0xffffffffu, ls, off);
    float invden = 1.f / fmaxf(ls, 1e-16f);
    float cs = exs * invden;
    __syncwarp();
#pragma unroll
    for (int q = 0; q < 4; q++) {
        int cidx = q * 32 + lane;
        float4 hv = ((const float4*)&g_h[n * 512])[cidx];
        float4 acc;
        acc.x = cs * hv.x; acc.y = cs * hv.y; acc.z = cs * hv.z; acc.w = cs * hv.w;
        for (int p = 0; p < deg; p++) {
            int s = wsrc[p];
            float c = wsal[p] * invden;
            float4 h4 = ((const float4*)&g_h[s * 512])[cidx];
            acc.x += c * h4.x; acc.y += c * h4.y; acc.z += c * h4.z; acc.w += c * h4.w;
        }
        // fused: relu(out + gbias) so ab_gemm reads activations directly
        float4 gb = ((const float4*)gbias)[cidx];
        acc.x = fmaxf(acc.x + gb.x, 0.f);
        acc.y = fmaxf(acc.y + gb.y, 0.f);
        acc.z = fmaxf(acc.z + gb.z, 0.f);
        acc.w = fmaxf(acc.w + gb.w, 0.f);
        ((float4*)&g_o512[n * 512])[cidx] = acc;
    }
}

// ---------------- AB GEMM: 32M x 128N tile, BK=16, 8x8/thread, 64 threads ----------------
// grid (188, 2): by=0 -> g_A (w1 rows 0..511), by=1 -> g_B (rows 512..1023)
__global__ void ab_gemm_k(const float* __restrict__ w1, const float* __restrict__ b1) {
    __shared__ float As[16][36];
    __shared__ float Bs[16][128];
    int tid = threadIdx.x;               // 64
    int bm = blockIdx.x * 32;
    int by = blockIdx.y;
    int ty = tid >> 4, tx = tid & 15;    // ty 0..3, tx 0..15
    float acc[8][8] = {};
    for (int k0 = 0; k0 < 512; k0 += 16) {
        {
            int mm = tid & 31, kg = tid >> 5;    // kg 0..1
            int gm = bm + mm;
#pragma unroll
            for (int r = 0; r < 2; r++) {
                int k = kg * 8 + r * 4;
                float4 v = make_float4(0.f, 0.f, 0.f, 0.f);
                if (gm < NN) v = *(const float4*)&g_o512[gm * 512 + k0 + k];
                As[k + 0][mm] = v.x;
                As[k + 1][mm] = v.y;
                As[k + 2][mm] = v.z;
                As[k + 3][mm] = v.w;
            }
        }
        {
            int id = tid * 4;
#pragma unroll
            for (int rep = 0; rep < 8; rep++, id += 256) {
                int kk = id >> 7, col = id & 127;
                *(float4*)&Bs[kk][col] = *(const float4*)&w1[(k0 + kk + by * 512) * 128 + col];
            }
        }
        __syncthreads();
#pragma unroll
        for (int kk = 0; kk < 16; kk++) {
            float a[8], bb[8];
#pragma unroll
            for (int i = 0; i < 8; i++) a[i] = As[kk][ty * 8 + i];
#pragma unroll
            for (int j = 0; j < 8; j++) bb[j] = Bs[kk][tx * 8 + j];
#pragma unroll
            for (int i = 0; i < 8; i++)
#pragma unroll
                for (int j = 0; j < 8; j++) acc[i][j] += a[i] * bb[j];
        }
        __syncthreads();
    }
#pragma unroll
    for (int i = 0; i < 8; i++) {
        int gm = bm + ty * 8 + i;
        if (gm >= NN) continue;
#pragma unroll
        for (int j = 0; j < 8; j++) {
            int c = tx * 8 + j;
            float v = acc[i][j];
            if (by == 0) v += b1[c];
            if (by == 0) g_A[gm * 128 + c] = v;
            else         g_B[gm * 128 + c] = v;
        }
    }
}

__global__ void final_k(const int* __restrict__ src, const int* __restrict__ dst,
                        const float* __restrict__ w2, const float* __restrict__ b2,
                        float* __restrict__ out) {
    int e = blockIdx.x * 4 + (threadIdx.x >> 5);
    int lane = threadIdx.x & 31;
    if (e >= EE) return;
    int s = src[e], d = dst[e];
    float4 a = *(const float4*)&g_A[s * 128 + lane * 4];
    float4 b = *(const float4*)&g_B[d * 128 + lane * 4];
    float4 w = *(const float4*)&w2[lane * 4];
    float sum = fmaxf(a.x + b.x, 0.f) * w.x + fmaxf(a.y + b.y, 0.f) * w.y +
                fmaxf(a.z + b.z, 0.f) * w.z + fmaxf(a.w + b.w, 0.f) * w.w;
#pragma unroll
    for (int off = 16; off; off >>= 1) sum += __shfl_down_sync(0xffffffffu, sum, off);
    if (lane == 0) out[e] = 1.f / (1.f + expf(-(sum + b2[0])));
}

// ---------------- host ----------------
extern "C" void kernel_launch(void* const* d_in, const int* in_sizes, int n_in,
                              void* d_out, int out_size) {
    int b = (in_sizes[0] == 2 * EE) ? 2 : 0;
    const int* eidx = (const int*)(b ? d_in[0] : d_in[24]);
    const int* etype = (const int*)(b ? d_in[1] : d_in[25]);
    const int* src = eidx;
    const int* dst = eidx + EE;
    auto F = [&](int i) { return (const float*)d_in[i]; };

    // fused init (zero counters + weight precompute), then CSR build
    int ptot = R0 + 4096 + 8192 + 4096;
    init_k<<<(ptot + 255) / 256, 256>>>(F(b + 0), F(b + 1), F(b + 4), F(b + 5),
                                        F(b + 8), F(b + 9), F(b + 12), F(b + 13));
    count_k<<<(EE + 255) / 256, 256>>>(etype, dst);
    scan_k<<<1, 1024>>>();
    scatter_k<<<(EE + 255) / 256, 256>>>(src, dst, etype);

    // layer 0
    l0_agg_k<<<NN / 4, 128>>>(F(b + 2), F(b + 3));

    // fused layers 1..3 (L1 x->y, L2 y->x, L3 x->y)
    dim3 blk(64, 4);
    layer_k<<<NN / 4, blk>>>(F(b + 6),  F(b + 7),  1, 32, 64, 0);
    layer_k<<<NN / 4, blk>>>(F(b + 10), F(b + 11), 2, 64, 64, 1);
    layer_k<<<NN / 4, blk>>>(F(b + 14), F(b + 15), 3, 64, 32, 0);

    // GAT (attn fused into gemm epilogue; gbias+relu fused into node epilogue)
    dim3 hg((NN + 63) / 64, 4);
    gath_gemm_k<<<hg, 256>>>(F(b + 16), F(b + 17), F(b + 18));
    gat_node_k<<<(NN + 3) / 4, 128>>>(F(b + 19));

    // edge MLP
    dim3 abgrid((NN + 31) / 32, 2);
    ab_gemm_k<<<abgrid, 64>>>(F(b + 20), F(b + 21));
    final_k<<<(EE + 3) / 4, 128>>>(src, dst, F(b + 22), F(b + 23), (float*)d_out);
}

// round 13
// speedup vs baseline: 1.4118x; 1.4118x over previous
#include <cuda_runtime.h>
#include <cuda_bf16.h>
#include <math.h>

#define NN 6000
#define EE 100000

// ---------------- scratch (device-only; NEVER passed from host) ----------------
__device__ float g_x[NN * 64];          // ping
__device__ float g_y[NN * 64];          // pong
__device__ float g_hr[2 * NN * 32];     // layer0 relation rows
__device__ float g_W1[32 * 128];        // [I, 2*O]
__device__ float g_W2[64 * 128];
__device__ float g_W3[64 * 64];
__device__ int   g_cnt[2 * NN];
__device__ float g_rinv[2 * NN];
__device__ int   g_offs[NN + 1];
__device__ int   g_cur[NN];
__device__ int   g_csr[EE];             // src | (rel<<16)
__device__ float g_h[NN * 512];
__device__ float g_asv[NN], g_adv[NN];
__device__ float g_o512[NN * 512];      // holds relu(gat_out + gbias)
__device__ float g_A[NN * 128], g_B[NN * 128];

// ---------------- fused init: zero counters + all weight precomputes ----------------
__device__ __forceinline__ void wcat_one(float* W, const float* basis, const float* comp,
                                         int I, int O, int i) {
    int r = i / (I * O), io = i % (I * O);
    float acc = 0.f;
#pragma unroll
    for (int b = 0; b < 4; b++) acc += comp[r * 4 + b] * basis[b * I * O + io];
    W[(io / O) * 2 * O + r * O + (io % O)] = acc;
}
#define R0 (2 * NN * 32)
__global__ void init_k(const float* __restrict__ basis0, const float* __restrict__ comp0,
                       const float* __restrict__ b1s, const float* __restrict__ c1,
                       const float* __restrict__ b2s, const float* __restrict__ c2,
                       const float* __restrict__ b3s, const float* __restrict__ c3) {
    int i = blockIdx.x * blockDim.x + threadIdx.x;
    if (i < 2 * NN) g_cnt[i] = 0;
    if (i < NN) { g_cur[i] = 0; g_asv[i] = 0.f; g_adv[i] = 0.f; }
    if (i < R0) {
        int r = i / (NN * 32), idx = i % (NN * 32);
        float acc = 0.f;
#pragma unroll
        for (int b = 0; b < 4; b++) acc += comp0[r * 4 + b] * basis0[b * NN * 32 + idx];
        g_hr[r * NN * 32 + idx] = acc;
    } else if (i < R0 + 4096) {
        wcat_one(g_W1, b1s, c1, 32, 64, i - R0);
    } else if (i < R0 + 4096 + 8192) {
        wcat_one(g_W2, b2s, c2, 64, 64, i - R0 - 4096);
    } else if (i < R0 + 4096 + 8192 + 4096) {
        wcat_one(g_W3, b3s, c3, 64, 32, i - R0 - 4096 - 8192);
    }
}

__global__ void count_k(const int* __restrict__ et, const int* __restrict__ dst) {
    int e = blockIdx.x * blockDim.x + threadIdx.x;
    if (e < EE) atomicAdd(&g_cnt[et[e] * NN + dst[e]], 1);
}
// scan of deg (=cnt0+cnt1) + rinv, single block 1024 threads
__global__ void scan_k() {
    __shared__ int ws[32];
    int t = threadIdx.x;
    for (int i = t; i < 2 * NN; i += 1024)
        g_rinv[i] = 1.0f / fmaxf((float)g_cnt[i], 1.0f);
    int base = t * 6;
    int loc[6]; int s = 0;
#pragma unroll
    for (int j = 0; j < 6; j++) {
        int idx = base + j; loc[j] = s;
        s += (idx < NN) ? (g_cnt[idx] + g_cnt[NN + idx]) : 0;
    }
    int lane = t & 31, w = t >> 5;
    int v = s;
#pragma unroll
    for (int off = 1; off < 32; off <<= 1) {
        int nv = __shfl_up_sync(0xffffffffu, v, off);
        if (lane >= off) v += nv;
    }
    if (lane == 31) ws[w] = v;
    __syncthreads();
    if (w == 0) {
        int x = ws[lane];
#pragma unroll
        for (int off = 1; off < 32; off <<= 1) {
            int nv = __shfl_up_sync(0xffffffffu, x, off);
            if (lane >= off) x += nv;
        }
        ws[lane] = x;
    }
    __syncthreads();
    int excl = v - s + (w ? ws[w - 1] : 0);
#pragma unroll
    for (int j = 0; j < 6; j++) {
        int idx = base + j;
        if (idx < NN) g_offs[idx] = excl + loc[j];
    }
    if (t == 1023) g_offs[NN] = excl + s;
}
__global__ void scatter_k(const int* __restrict__ src, const int* __restrict__ dst,
                          const int* __restrict__ et) {
    int e = blockIdx.x * blockDim.x + threadIdx.x;
    if (e >= EE) return;
    int d = dst[e];
    int pos = g_offs[d] + atomicAdd(&g_cur[d], 1);
    g_csr[pos] = src[e] | (et[e] << 16);
}

// ---------------- layer 0: gather + root + bias + tanh ----------------
__global__ void l0_agg_k(const float* __restrict__ root0, const float* __restrict__ rbias0) {
    int n = blockIdx.x * 4 + (threadIdx.x >> 5);
    int lane = threadIdx.x & 31;
    if (n >= NN) return;
    int o = g_offs[n], e2 = g_offs[n + 1];
    float a0 = 0.f, a1 = 0.f;
    for (int p = o; p < e2; p++) {
        int pk = g_csr[p];
        float v = g_hr[(pk >> 16) * NN * 32 + (pk & 0xffff) * 32 + lane];
        if (pk & 0x10000) a1 += v; else a0 += v;
    }
    float out = root0[n * 32 + lane] + rbias0[lane] + a0 * g_rinv[n] + a1 * g_rinv[NN + n];
    g_x[n * 32 + lane] = tanhf(out);
}

// ---------------- fused RGCN layer: aggregate + GEMM + tanh ----------------
__global__ void layer_k(const float* __restrict__ root, const float* __restrict__ rbias,
                        int layer, int I, int O, int inflag) {
    __shared__ float xs[4][64], a0s[4][64], a1s[4][64];
    const float* xin = inflag ? g_y : g_x;
    float* xout = inflag ? g_x : g_y;
    const float* Wcat = (layer == 1) ? g_W1 : (layer == 2) ? g_W2 : g_W3;
    int ty = threadIdx.y, tx = threadIdx.x;
    int n = blockIdx.x * 4 + ty;
    if (tx < I) {
        int o = g_offs[n], e2 = g_offs[n + 1];
        float a0 = 0.f, a1 = 0.f;
#pragma unroll 4
        for (int p = o; p < e2; p++) {
            int pk = g_csr[p];
            float v = xin[(pk & 0xffff) * I + tx];
            if (pk & 0x10000) a1 += v; else a0 += v;
        }
        xs[ty][tx] = xin[n * I + tx];
        a0s[ty][tx] = a0 * g_rinv[n];
        a1s[ty][tx] = a1 * g_rinv[NN + n];
    }
    __syncthreads();
    if (tx < O) {
        float acc = rbias[tx];
#pragma unroll 8
        for (int i = 0; i < I; i++) {
            acc += xs[ty][i] * root[i * O + tx];
            acc += a0s[ty][i] * Wcat[i * 2 * O + tx];
            acc += a1s[ty][i] * Wcat[i * 2 * O + O + tx];
        }
        xout[n * O + tx] = tanhf(acc);
    }
}

// ---------------- GAT h GEMM + fused attention partials ----------------
__global__ void gath_gemm_k(const float* __restrict__ gw, const float* __restrict__ asrc,
                            const float* __restrict__ adst) {
    __shared__ float As[32][68];
    __shared__ float Bs[32][128];
    int tid = threadIdx.x;
    int bm = blockIdx.x * 64, bn = blockIdx.y * 128;
    int ty = tid >> 4, tx = tid & 15;
    {
        int mm = tid & 63, kg = tid >> 6;
#pragma unroll
        for (int r = 0; r < 2; r++) {
            int k = kg * 8 + r * 4;
            int gm = bm + mm;
            float4 v = make_float4(0.f, 0.f, 0.f, 0.f);
            if (gm < NN) v = *(const float4*)&g_y[gm * 32 + k];
            As[k + 0][mm] = v.x; As[k + 1][mm] = v.y;
            As[k + 2][mm] = v.z; As[k + 3][mm] = v.w;
        }
    }
    {
        int id = tid * 4;
#pragma unroll
        for (int rep = 0; rep < 4; rep++, id += 1024) {
            int kk = id >> 7, col = id & 127;
            *(float4*)&Bs[kk][col] = *(const float4*)&gw[kk * 512 + bn + col];
        }
    }
    __syncthreads();
    float acc[4][8] = {};
#pragma unroll
    for (int kk = 0; kk < 32; kk++) {
        float a[4], bb[8];
#pragma unroll
        for (int i = 0; i < 4; i++) a[i] = As[kk][ty * 4 + i];
#pragma unroll
        for (int j = 0; j < 8; j++) bb[j] = Bs[kk][tx * 8 + j];
#pragma unroll
        for (int i = 0; i < 4; i++)
#pragma unroll
            for (int j = 0; j < 8; j++) acc[i][j] += a[i] * bb[j];
    }
#pragma unroll
    for (int i = 0; i < 4; i++) {
        int gm = bm + ty * 4 + i;
        if (gm >= NN) continue;
#pragma unroll
        for (int j = 0; j < 8; j += 4) {
            float4 st = make_float4(acc[i][j], acc[i][j + 1], acc[i][j + 2], acc[i][j + 3]);
            *(float4*)&g_h[gm * 512 + bn + tx * 8 + j] = st;
        }
    }
    float sa[8], da[8];
#pragma unroll
    for (int j = 0; j < 8; j++) {
        sa[j] = asrc[bn + tx * 8 + j];
        da[j] = adst[bn + tx * 8 + j];
    }
#pragma unroll
    for (int i = 0; i < 4; i++) {
        float pa = 0.f, pd = 0.f;
#pragma unroll
        for (int j = 0; j < 8; j++) { pa += acc[i][j] * sa[j]; pd += acc[i][j] * da[j]; }
#pragma unroll
        for (int off = 8; off; off >>= 1) {
            pa += __shfl_down_sync(0xffffffffu, pa, off, 16);
            pd += __shfl_down_sync(0xffffffffu, pd, off, 16);
        }
        int gm = bm + ty * 4 + i;
        if (tx == 0 && gm < NN) {
            atomicAdd(&g_asv[gm], pa);
            atomicAdd(&g_adv[gm], pd);
        }
    }
}

// ---------------- GAT softmax + weighted sum + fused gbias/relu ----------------
__global__ void gat_node_k(const float* __restrict__ gbias) {
    __shared__ float sal[4][512];
    __shared__ int ssrc[4][512];
    int wid = threadIdx.x >> 5, lane = threadIdx.x & 31;
    int n = blockIdx.x * 4 + wid;
    if (n >= NN) return;
    int o = g_offs[n];
    int deg = g_offs[n + 1] - o;
    if (deg > 512) deg = 512;
    float advn = g_adv[n];
    float* wsal = sal[wid];
    int* wsrc = ssrc[wid];
    float lm = -1e30f;
    for (int p = lane; p < deg; p += 32) {
        int s = g_csr[o + p] & 0xffff;
        wsrc[p] = s;
        float a = g_asv[s] + advn;
        a = a > 0.f ? a : 0.2f * a;
        wsal[p] = a;
        lm = fmaxf(lm, a);
    }
    float als = g_asv[n] + advn;
    als = als > 0.f ? als : 0.2f * als;
    lm = fmaxf(lm, als);
#pragma unroll
    for (int off = 16; off; off >>= 1)
        lm = fmaxf(lm, __shfl_xor_sync(0xffffffffu, lm, off));
    float m = lm;
    float ls = 0.f;
    __syncwarp();
    for (int p = lane; p < deg; p += 32) {
        float ex = expf(wsal[p] - m);
        wsal[p] = ex;
        ls += ex;
    }
    float exs = expf(als - m);
    if (lane == 0) ls += exs;
#pragma unroll
    for (int off = 16; off; off >>= 1)
        ls += __shfl_xor_sync(0xffffffffu, ls, off);
    float invden = 1.f / fmaxf(ls, 1e-16f);
    float cs = exs * invden;
    __syncwarp();
#pragma unroll
    for (int q = 0; q < 4; q++) {
        int cidx = q * 32 + lane;
        float4 hv = ((const float4*)&g_h[n * 512])[cidx];
        float4 acc;
        acc.x = cs * hv.x; acc.y = cs * hv.y; acc.z = cs * hv.z; acc.w = cs * hv.w;
        for (int p = 0; p < deg; p++) {
            int s = wsrc[p];
            float c = wsal[p] * invden;
            float4 h4 = ((const float4*)&g_h[s * 512])[cidx];
            acc.x += c * h4.x; acc.y += c * h4.y; acc.z += c * h4.z; acc.w += c * h4.w;
        }
        float4 gb = ((const float4*)gbias)[cidx];
        acc.x = fmaxf(acc.x + gb.x, 0.f);
        acc.y = fmaxf(acc.y + gb.y, 0.f);
        acc.z = fmaxf(acc.z + gb.z, 0.f);
        acc.w = fmaxf(acc.w + gb.w, 0.f);
        ((float4*)&g_o512[n * 512])[cidx] = acc;
    }
}

// ---------------- AB GEMM (reverted to R9 config): 64M x 128N, BK=16, 8x8/thread, 128 thr ----------------
__global__ void ab_gemm_k(const float* __restrict__ w1, const float* __restrict__ b1) {
    __shared__ float As[16][68];
    __shared__ float Bs[16][128];
    int tid = threadIdx.x;               // 128
    int bm = blockIdx.x * 64;
    int by = blockIdx.y;                 // 0 -> g_A half, 1 -> g_B half
    int ty = tid >> 4, tx = tid & 15;    // ty 0..7, tx 0..15
    float acc[8][8] = {};
    for (int k0 = 0; k0 < 512; k0 += 16) {
        {
            int mm = tid & 63, kg = tid >> 6;    // kg 0..1, each covers 8 k's
            int gm = bm + mm;
#pragma unroll
            for (int r = 0; r < 2; r++) {
                int k = kg * 8 + r * 4;
                float4 v = make_float4(0.f, 0.f, 0.f, 0.f);
                if (gm < NN) v = *(const float4*)&g_o512[gm * 512 + k0 + k];
                As[k + 0][mm] = v.x;
                As[k + 1][mm] = v.y;
                As[k + 2][mm] = v.z;
                As[k + 3][mm] = v.w;
            }
        }
        {
            int id = tid * 4;
#pragma unroll
            for (int rep = 0; rep < 4; rep++, id += 512) {
                int kk = id >> 7, col = id & 127;
                *(float4*)&Bs[kk][col] = *(const float4*)&w1[(k0 + kk + by * 512) * 128 + col];
            }
        }
        __syncthreads();
#pragma unroll
        for (int kk = 0; kk < 16; kk++) {
            float a[8], bb[8];
#pragma unroll
            for (int i = 0; i < 8; i++) a[i] = As[kk][((ty & 3) * 8 + i) + (ty >> 2) * 32];
#pragma unroll
            for (int j = 0; j < 8; j++) bb[j] = Bs[kk][tx * 8 + j];
#pragma unroll
            for (int i = 0; i < 8; i++)
#pragma unroll
                for (int j = 0; j < 8; j++) acc[i][j] += a[i] * bb[j];
        }
        __syncthreads();
    }
#pragma unroll
    for (int i = 0; i < 8; i++) {
        int gm = bm + ((ty & 3) * 8 + i) + (ty >> 2) * 32;
        if (gm >= NN) continue;
#pragma unroll
        for (int j = 0; j < 8; j++) {
            int c = tx * 8 + j;
            float v = acc[i][j];
            if (by == 0) v += b1[c];
            if (by == 0) g_A[gm * 128 + c] = v;
            else         g_B[gm * 128 + c] = v;
        }
    }
}

__global__ void final_k(const int* __restrict__ src, const int* __restrict__ dst,
                        const float* __restrict__ w2, const float* __restrict__ b2,
                        float* __restrict__ out) {
    int e = blockIdx.x * 4 + (threadIdx.x >> 5);
    int lane = threadIdx.x & 31;
    if (e >= EE) return;
    int s = src[e], d = dst[e];
    float4 a = *(const float4*)&g_A[s * 128 + lane * 4];
    float4 b = *(const float4*)&g_B[d * 128 + lane * 4];
    float4 w = *(const float4*)&w2[lane * 4];
    float sum = fmaxf(a.x + b.x, 0.f) * w.x + fmaxf(a.y + b.y, 0.f) * w.y +
                fmaxf(a.z + b.z, 0.f) * w.z + fmaxf(a.w + b.w, 0.f) * w.w;
#pragma unroll
    for (int off = 16; off; off >>= 1) sum += __shfl_down_sync(0xffffffffu, sum, off);
    if (lane == 0) out[e] = 1.f / (1.f + expf(-(sum + b2[0])));
}

// ---------------- host ----------------
extern "C" void kernel_launch(void* const* d_in, const int* in_sizes, int n_in,
                              void* d_out, int out_size) {
    int b = (in_sizes[0] == 2 * EE) ? 2 : 0;
    const int* eidx = (const int*)(b ? d_in[0] : d_in[24]);
    const int* etype = (const int*)(b ? d_in[1] : d_in[25]);
    const int* src = eidx;
    const int* dst = eidx + EE;
    auto F = [&](int i) { return (const float*)d_in[i]; };

    // fused init (zero counters + weight precompute), then CSR build
    int ptot = R0 + 4096 + 8192 + 4096;
    init_k<<<(ptot + 255) / 256, 256>>>(F(b + 0), F(b + 1), F(b + 4), F(b + 5),
                                        F(b + 8), F(b + 9), F(b + 12), F(b + 13));
    count_k<<<(EE + 255) / 256, 256>>>(etype, dst);
    scan_k<<<1, 1024>>>();
    scatter_k<<<(EE + 255) / 256, 256>>>(src, dst, etype);

    // layer 0
    l0_agg_k<<<NN / 4, 128>>>(F(b + 2), F(b + 3));

    // fused layers 1..3 (L1 x->y, L2 y->x, L3 x->y)
    dim3 blk(64, 4);
    layer_k<<<NN / 4, blk>>>(F(b + 6),  F(b + 7),  1, 32, 64, 0);
    layer_k<<<NN / 4, blk>>>(F(b + 10), F(b + 11), 2, 64, 64, 1);
    layer_k<<<NN / 4, blk>>>(F(b + 14), F(b + 15), 3, 64, 32, 0);

    // GAT (attn fused into gemm epilogue; gbias+relu fused into node epilogue)
    dim3 hg((NN + 63) / 64, 4);
    gath_gemm_k<<<hg, 256>>>(F(b + 16), F(b + 17), F(b + 18));
    gat_node_k<<<(NN + 3) / 4, 128>>>(F(b + 19));

    // edge MLP
    dim3 abgrid((NN + 63) / 64, 2);
    ab_gemm_k<<<abgrid, 128>>>(F(b + 20), F(b + 21));
    final_k<<<(EE + 3) / 4, 128>>>(src, dst, F(b + 22), F(b + 23), (float*)d_out);
}

// round 14
// speedup vs baseline: 1.4346x; 1.0162x over previous
#include <cuda_runtime.h>
#include <cuda_bf16.h>
#include <mma.h>
#include <math.h>

using namespace nvcuda;

#define NN 6000
#define EE 100000

// ---------------- scratch (device-only; NEVER passed from host) ----------------
__device__ float g_x[NN * 64];          // ping
__device__ float g_y[NN * 64];          // pong
__device__ float g_hr[2 * NN * 32];     // layer0 relation rows
__device__ float g_W1[32 * 128];        // [I, 2*O]
__device__ float g_W2[64 * 128];
__device__ float g_W3[64 * 64];
__device__ int   g_cnt[2 * NN];
__device__ float g_rinv[2 * NN];
__device__ int   g_offs[NN + 1];
__device__ int   g_cur[NN];
__device__ int   g_csr[EE];             // src | (rel<<16)
__device__ float g_h[NN * 512];
__device__ float g_asv[NN], g_adv[NN];
__device__ float g_o512[NN * 512];      // holds relu(gat_out + gbias)
__device__ float g_A[NN * 128], g_B[NN * 128];

// ---------------- fused init: zero counters + all weight precomputes ----------------
__device__ __forceinline__ void wcat_one(float* W, const float* basis, const float* comp,
                                         int I, int O, int i) {
    int r = i / (I * O), io = i % (I * O);
    float acc = 0.f;
#pragma unroll
    for (int b = 0; b < 4; b++) acc += comp[r * 4 + b] * basis[b * I * O + io];
    W[(io / O) * 2 * O + r * O + (io % O)] = acc;
}
#define R0 (2 * NN * 32)
__global__ void init_k(const float* __restrict__ basis0, const float* __restrict__ comp0,
                       const float* __restrict__ b1s, const float* __restrict__ c1,
                       const float* __restrict__ b2s, const float* __restrict__ c2,
                       const float* __restrict__ b3s, const float* __restrict__ c3) {
    int i = blockIdx.x * blockDim.x + threadIdx.x;
    if (i < 2 * NN) g_cnt[i] = 0;
    if (i < NN) { g_cur[i] = 0; g_asv[i] = 0.f; g_adv[i] = 0.f; }
    if (i < R0) {
        int r = i / (NN * 32), idx = i % (NN * 32);
        float acc = 0.f;
#pragma unroll
        for (int b = 0; b < 4; b++) acc += comp0[r * 4 + b] * basis0[b * NN * 32 + idx];
        g_hr[r * NN * 32 + idx] = acc;
    } else if (i < R0 + 4096) {
        wcat_one(g_W1, b1s, c1, 32, 64, i - R0);
    } else if (i < R0 + 4096 + 8192) {
        wcat_one(g_W2, b2s, c2, 64, 64, i - R0 - 4096);
    } else if (i < R0 + 4096 + 8192 + 4096) {
        wcat_one(g_W3, b3s, c3, 64, 32, i - R0 - 4096 - 8192);
    }
}

__global__ void count_k(const int* __restrict__ et, const int* __restrict__ dst) {
    int e = blockIdx.x * blockDim.x + threadIdx.x;
    if (e < EE) atomicAdd(&g_cnt[et[e] * NN + dst[e]], 1);
}
// scan of deg (=cnt0+cnt1) + rinv, single block 1024 threads
__global__ void scan_k() {
    __shared__ int ws[32];
    int t = threadIdx.x;
    for (int i = t; i < 2 * NN; i += 1024)
        g_rinv[i] = 1.0f / fmaxf((float)g_cnt[i], 1.0f);
    int base = t * 6;
    int loc[6]; int s = 0;
#pragma unroll
    for (int j = 0; j < 6; j++) {
        int idx = base + j; loc[j] = s;
        s += (idx < NN) ? (g_cnt[idx] + g_cnt[NN + idx]) : 0;
    }
    int lane = t & 31, w = t >> 5;
    int v = s;
#pragma unroll
    for (int off = 1; off < 32; off <<= 1) {
        int nv = __shfl_up_sync(0xffffffffu, v, off);
        if (lane >= off) v += nv;
    }
    if (lane == 31) ws[w] = v;
    __syncthreads();
    if (w == 0) {
        int x = ws[lane];
#pragma unroll
        for (int off = 1; off < 32; off <<= 1) {
            int nv = __shfl_up_sync(0xffffffffu, x, off);
            if (lane >= off) x += nv;
        }
        ws[lane] = x;
    }
    __syncthreads();
    int excl = v - s + (w ? ws[w - 1] : 0);
#pragma unroll
    for (int j = 0; j < 6; j++) {
        int idx = base + j;
        if (idx < NN) g_offs[idx] = excl + loc[j];
    }
    if (t == 1023) g_offs[NN] = excl + s;
}
__global__ void scatter_k(const int* __restrict__ src, const int* __restrict__ dst,
                          const int* __restrict__ et) {
    int e = blockIdx.x * blockDim.x + threadIdx.x;
    if (e >= EE) return;
    int d = dst[e];
    int pos = g_offs[d] + atomicAdd(&g_cur[d], 1);
    g_csr[pos] = src[e] | (et[e] << 16);
}

// ---------------- layer 0: gather + root + bias + tanh ----------------
__global__ void l0_agg_k(const float* __restrict__ root0, const float* __restrict__ rbias0) {
    int n = blockIdx.x * 4 + (threadIdx.x >> 5);
    int lane = threadIdx.x & 31;
    if (n >= NN) return;
    int o = g_offs[n], e2 = g_offs[n + 1];
    float a0 = 0.f, a1 = 0.f;
    for (int p = o; p < e2; p++) {
        int pk = g_csr[p];
        float v = g_hr[(pk >> 16) * NN * 32 + (pk & 0xffff) * 32 + lane];
        if (pk & 0x10000) a1 += v; else a0 += v;
    }
    float out = root0[n * 32 + lane] + rbias0[lane] + a0 * g_rinv[n] + a1 * g_rinv[NN + n];
    g_x[n * 32 + lane] = tanhf(out);
}

// ---------------- fused RGCN layer: aggregate + GEMM + tanh ----------------
__global__ void layer_k(const float* __restrict__ root, const float* __restrict__ rbias,
                        int layer, int I, int O, int inflag) {
    __shared__ float xs[4][64], a0s[4][64], a1s[4][64];
    const float* xin = inflag ? g_y : g_x;
    float* xout = inflag ? g_x : g_y;
    const float* Wcat = (layer == 1) ? g_W1 : (layer == 2) ? g_W2 : g_W3;
    int ty = threadIdx.y, tx = threadIdx.x;
    int n = blockIdx.x * 4 + ty;
    if (tx < I) {
        int o = g_offs[n], e2 = g_offs[n + 1];
        float a0 = 0.f, a1 = 0.f;
#pragma unroll 4
        for (int p = o; p < e2; p++) {
            int pk = g_csr[p];
            float v = xin[(pk & 0xffff) * I + tx];
            if (pk & 0x10000) a1 += v; else a0 += v;
        }
        xs[ty][tx] = xin[n * I + tx];
        a0s[ty][tx] = a0 * g_rinv[n];
        a1s[ty][tx] = a1 * g_rinv[NN + n];
    }
    __syncthreads();
    if (tx < O) {
        float acc = rbias[tx];
#pragma unroll 8
        for (int i = 0; i < I; i++) {
            acc += xs[ty][i] * root[i * O + tx];
            acc += a0s[ty][i] * Wcat[i * 2 * O + tx];
            acc += a1s[ty][i] * Wcat[i * 2 * O + O + tx];
        }
        xout[n * O + tx] = tanhf(acc);
    }
}

// ---------------- GAT h GEMM + fused attention partials ----------------
__global__ void gath_gemm_k(const float* __restrict__ gw, const float* __restrict__ asrc,
                            const float* __restrict__ adst) {
    __shared__ float As[32][68];
    __shared__ float Bs[32][128];
    int tid = threadIdx.x;
    int bm = blockIdx.x * 64, bn = blockIdx.y * 128;
    int ty = tid >> 4, tx = tid & 15;
    {
        int mm = tid & 63, kg = tid >> 6;
#pragma unroll
        for (int r = 0; r < 2; r++) {
            int k = kg * 8 + r * 4;
            int gm = bm + mm;
            float4 v = make_float4(0.f, 0.f, 0.f, 0.f);
            if (gm < NN) v = *(const float4*)&g_y[gm * 32 + k];
            As[k + 0][mm] = v.x; As[k + 1][mm] = v.y;
            As[k + 2][mm] = v.z; As[k + 3][mm] = v.w;
        }
    }
    {
        int id = tid * 4;
#pragma unroll
        for (int rep = 0; rep < 4; rep++, id += 1024) {
            int kk = id >> 7, col = id & 127;
            *(float4*)&Bs[kk][col] = *(const float4*)&gw[kk * 512 + bn + col];
        }
    }
    __syncthreads();
    float acc[4][8] = {};
#pragma unroll
    for (int kk = 0; kk < 32; kk++) {
        float a[4], bb[8];
#pragma unroll
        for (int i = 0; i < 4; i++) a[i] = As[kk][ty * 4 + i];
#pragma unroll
        for (int j = 0; j < 8; j++) bb[j] = Bs[kk][tx * 8 + j];
#pragma unroll
        for (int i = 0; i < 4; i++)
#pragma unroll
            for (int j = 0; j < 8; j++) acc[i][j] += a[i] * bb[j];
    }
#pragma unroll
    for (int i = 0; i < 4; i++) {
        int gm = bm + ty * 4 + i;
        if (gm >= NN) continue;
#pragma unroll
        for (int j = 0; j < 8; j += 4) {
            float4 st = make_float4(acc[i][j], acc[i][j + 1], acc[i][j + 2], acc[i][j + 3]);
            *(float4*)&g_h[gm * 512 + bn + tx * 8 + j] = st;
        }
    }
    float sa[8], da[8];
#pragma unroll
    for (int j = 0; j < 8; j++) {
        sa[j] = asrc[bn + tx * 8 + j];
        da[j] = adst[bn + tx * 8 + j];
    }
#pragma unroll
    for (int i = 0; i < 4; i++) {
        float pa = 0.f, pd = 0.f;
#pragma unroll
        for (int j = 0; j < 8; j++) { pa += acc[i][j] * sa[j]; pd += acc[i][j] * da[j]; }
#pragma unroll
        for (int off = 8; off; off >>= 1) {
            pa += __shfl_down_sync(0xffffffffu, pa, off, 16);
            pd += __shfl_down_sync(0xffffffffu, pd, off, 16);
        }
        int gm = bm + ty * 4 + i;
        if (tx == 0 && gm < NN) {
            atomicAdd(&g_asv[gm], pa);
            atomicAdd(&g_adv[gm], pd);
        }
    }
}

// ---------------- GAT softmax + weighted sum + fused gbias/relu ----------------
__global__ void gat_node_k(const float* __restrict__ gbias) {
    __shared__ float sal[4][512];
    __shared__ int ssrc[4][512];
    int wid = threadIdx.x >> 5, lane = threadIdx.x & 31;
    int n = blockIdx.x * 4 + wid;
    if (n >= NN) return;
    int o = g_offs[n];
    int deg = g_offs[n + 1] - o;
    if (deg > 512) deg = 512;
    float advn = g_adv[n];
    float* wsal = sal[wid];
    int* wsrc = ssrc[wid];
    float lm = -1e30f;
    for (int p = lane; p < deg; p += 32) {
        int s = g_csr[o + p] & 0xffff;
        wsrc[p] = s;
        float a = g_asv[s] + advn;
        a = a > 0.f ? a : 0.2f * a;
        wsal[p] = a;
        lm = fmaxf(lm, a);
    }
    float als = g_asv[n] + advn;
    als = als > 0.f ? als : 0.2f * als;
    lm = fmaxf(lm, als);
#pragma unroll
    for (int off = 16; off; off >>= 1)
        lm = fmaxf(lm, __shfl_xor_sync(0xffffffffu, lm, off));
    float m = lm;
    float ls = 0.f;
    __syncwarp();
    for (int p = lane; p < deg; p += 32) {
        float ex = expf(wsal[p] - m);
        wsal[p] = ex;
        ls += ex;
    }
    float exs = expf(als - m);
    if (lane == 0) ls += exs;
#pragma unroll
    for (int off = 16; off; off >>= 1)
        ls += __shfl_xor_sync(0xffffffffu, ls, off);
    float invden = 1.f / fmaxf(ls, 1e-16f);
    float cs = exs * invden;
    __syncwarp();
#pragma unroll
    for (int q = 0; q < 4; q++) {
        int cidx = q * 32 + lane;
        float4 hv = ((const float4*)&g_h[n * 512])[cidx];
        float4 acc;
        acc.x = cs * hv.x; acc.y = cs * hv.y; acc.z = cs * hv.z; acc.w = cs * hv.w;
        for (int p = 0; p < deg; p++) {
            int s = wsrc[p];
            float c = wsal[p] * invden;
            float4 h4 = ((const float4*)&g_h[s * 512])[cidx];
            acc.x += c * h4.x; acc.y += c * h4.y; acc.z += c * h4.z; acc.w += c * h4.w;
        }
        float4 gb = ((const float4*)gbias)[cidx];
        acc.x = fmaxf(acc.x + gb.x, 0.f);
        acc.y = fmaxf(acc.y + gb.y, 0.f);
        acc.z = fmaxf(acc.z + gb.z, 0.f);
        acc.w = fmaxf(acc.w + gb.w, 0.f);
        ((float4*)&g_o512[n * 512])[cidx] = acc;
    }
}

// ---------------- AB GEMM on tensor cores (wmma tf32): 64M x 128N, BK=32, 8 warps ----------------
// warps 2x4, each warp 32x32 = 2x2 m16n16k8 fragments. fp32 accumulate.
__global__ void ab_gemm_k(const float* __restrict__ w1, const float* __restrict__ b1) {
    __shared__ __align__(16) float sbuf[8192];     // 32 KB: As(2048) + Bs(4096), reused as Os(8192)
    float (*As)[32]  = (float(*)[32])sbuf;         // [64][32]
    float (*Bs)[128] = (float(*)[128])(sbuf + 2048); // [32][128]
    float (*Os)[128] = (float(*)[128])sbuf;        // [64][128] epilogue

    int tid = threadIdx.x;                 // 256
    int wid = tid >> 5;
    int warpRow = wid >> 2;                // 0..1
    int warpCol = wid & 3;                 // 0..3
    int bm = blockIdx.x * 64;
    int by = blockIdx.y;                   // 0 -> g_A (w1 rows 0..511), 1 -> g_B

    wmma::fragment<wmma::accumulator, 16, 16, 8, float> c[2][2];
#pragma unroll
    for (int i = 0; i < 2; i++)
#pragma unroll
        for (int j = 0; j < 2; j++) wmma::fill_fragment(c[i][j], 0.f);

    for (int k0 = 0; k0 < 512; k0 += 32) {
        // load A: 64 rows x 32 k (row-major [m][k]); 8 floats/thread
        {
            int mm = tid & 63, kg = tid >> 6;      // kg 0..3 -> 8 k's each
            int gm = bm + mm;
#pragma unroll
            for (int r = 0; r < 2; r++) {
                int k = kg * 8 + r * 4;
                float4 v = make_float4(0.f, 0.f, 0.f, 0.f);
                if (gm < NN) v = *(const float4*)&g_o512[gm * 512 + k0 + k];
                As[mm][k + 0] = wmma::__float_to_tf32(v.x);
                As[mm][k + 1] = wmma::__float_to_tf32(v.y);
                As[mm][k + 2] = wmma::__float_to_tf32(v.z);
                As[mm][k + 3] = wmma::__float_to_tf32(v.w);
            }
        }
        // load B: 32 k x 128 n (row-major [k][n]); 16 floats/thread
        {
            int id = tid * 4;
#pragma unroll
            for (int rep = 0; rep < 4; rep++, id += 1024) {
                int kk = id >> 7, col = id & 127;
                float4 v = *(const float4*)&w1[(k0 + kk + by * 512) * 128 + col];
                Bs[kk][col + 0] = wmma::__float_to_tf32(v.x);
                Bs[kk][col + 1] = wmma::__float_to_tf32(v.y);
                Bs[kk][col + 2] = wmma::__float_to_tf32(v.z);
                Bs[kk][col + 3] = wmma::__float_to_tf32(v.w);
            }
        }
        __syncthreads();
#pragma unroll
        for (int ks = 0; ks < 4; ks++) {
            wmma::fragment<wmma::matrix_a, 16, 16, 8, wmma::precision::tf32, wmma::row_major> a[2];
            wmma::fragment<wmma::matrix_b, 16, 16, 8, wmma::precision::tf32, wmma::row_major> bf[2];
#pragma unroll
            for (int i = 0; i < 2; i++)
                wmma::load_matrix_sync(a[i], &As[warpRow * 32 + i * 16][ks * 8], 32);
#pragma unroll
            for (int j = 0; j < 2; j++)
                wmma::load_matrix_sync(bf[j], &Bs[ks * 8][warpCol * 32 + j * 16], 128);
#pragma unroll
            for (int i = 0; i < 2; i++)
#pragma unroll
                for (int j = 0; j < 2; j++)
                    wmma::mma_sync(c[i][j], a[i], bf[j], c[i][j]);
        }
        __syncthreads();
    }
    // epilogue: stage through smem, add bias, store fp32
#pragma unroll
    for (int i = 0; i < 2; i++)
#pragma unroll
        for (int j = 0; j < 2; j++)
            wmma::store_matrix_sync(&Os[warpRow * 32 + i * 16][warpCol * 32 + j * 16],
                                    c[i][j], 128, wmma::mem_row_major);
    __syncthreads();
    {
        int id = tid * 4;
#pragma unroll
        for (int rep = 0; rep < 8; rep++, id += 1024) {
            int row = id >> 7, col = id & 127;
            int gm = bm + row;
            if (gm >= NN) continue;
            float4 v = *(const float4*)&Os[row][col];
            if (by == 0) {
                const float4 bb = *(const float4*)&b1[col];
                v.x += bb.x; v.y += bb.y; v.z += bb.z; v.w += bb.w;
                *(float4*)&g_A[gm * 128 + col] = v;
            } else {
                *(float4*)&g_B[gm * 128 + col] = v;
            }
        }
    }
}

__global__ void final_k(const int* __restrict__ src, const int* __restrict__ dst,
                        const float* __restrict__ w2, const float* __restrict__ b2,
                        float* __restrict__ out) {
    int e = blockIdx.x * 4 + (threadIdx.x >> 5);
    int lane = threadIdx.x & 31;
    if (e >= EE) return;
    int s = src[e], d = dst[e];
    float4 a = *(const float4*)&g_A[s * 128 + lane * 4];
    float4 b = *(const float4*)&g_B[d * 128 + lane * 4];
    float4 w = *(const float4*)&w2[lane * 4];
    float sum = fmaxf(a.x + b.x, 0.f) * w.x + fmaxf(a.y + b.y, 0.f) * w.y +
                fmaxf(a.z + b.z, 0.f) * w.z + fmaxf(a.w + b.w, 0.f) * w.w;
#pragma unroll
    for (int off = 16; off; off >>= 1) sum += __shfl_down_sync(0xffffffffu, sum, off);
    if (lane == 0) out[e] = 1.f / (1.f + expf(-(sum + b2[0])));
}

// ---------------- host ----------------
extern "C" void kernel_launch(void* const* d_in, const int* in_sizes, int n_in,
                              void* d_out, int out_size) {
    int b = (in_sizes[0] == 2 * EE) ? 2 : 0;
    const int* eidx = (const int*)(b ? d_in[0] : d_in[24]);
    const int* etype = (const int*)(b ? d_in[1] : d_in[25]);
    const int* src = eidx;
    const int* dst = eidx + EE;
    auto F = [&](int i) { return (const float*)d_in[i]; };

    // fused init (zero counters + weight precompute), then CSR build
    int ptot = R0 + 4096 + 8192 + 4096;
    init_k<<<(ptot + 255) / 256, 256>>>(F(b + 0), F(b + 1), F(b + 4), F(b + 5),
                                        F(b + 8), F(b + 9), F(b + 12), F(b + 13));
    count_k<<<(EE + 255) / 256, 256>>>(etype, dst);
    scan_k<<<1, 1024>>>();
    scatter_k<<<(EE + 255) / 256, 256>>>(src, dst, etype);

    // layer 0
    l0_agg_k<<<NN / 4, 128>>>(F(b + 2), F(b + 3));

    // fused layers 1..3 (L1 x->y, L2 y->x, L3 x->y)
    dim3 blk(64, 4);
    layer_k<<<NN / 4, blk>>>(F(b + 6),  F(b + 7),  1, 32, 64, 0);
    layer_k<<<NN / 4, blk>>>(F(b + 10), F(b + 11), 2, 64, 64, 1);
    layer_k<<<NN / 4, blk>>>(F(b + 14), F(b + 15), 3, 64, 32, 0);

    // GAT (attn fused into gemm epilogue; gbias+relu fused into node epilogue)
    dim3 hg((NN + 63) / 64, 4);
    gath_gemm_k<<<hg, 256>>>(F(b + 16), F(b + 17), F(b + 18));
    gat_node_k<<<(NN + 3) / 4, 128>>>(F(b + 19));

    // edge MLP (tensor-core tf32)
    dim3 abgrid((NN + 63) / 64, 2);
    ab_gemm_k<<<abgrid, 256>>>(F(b + 20), F(b + 21));
    final_k<<<(EE + 3) / 4, 128>>>(src, dst, F(b + 22), F(b + 23), (float*)d_out);
}